// round 3
// baseline (speedup 1.0000x reference)
#include <cuda_runtime.h>

// Problem constants (fixed shapes)
#define BB 4
#define CC 16
#define TT 2048
#define FF 32
#define JJ 256
#define KK 2049          // MAX_T + 1 (odd kernel)
#define HALF 1024
#define PP 512           // 2 time taps per token
#define RGROUP 4
#define NGROUP (FF/RGROUP)

#define TWO_PI_F 6.28318530717958647692f

// Scratch (device globals; no allocation allowed)
__device__ float2 g_wav[BB*FF*KK];   // normalized wavelet (wr, wi), interleaved
__device__ float2 g_V[BB*FF*CC*PP];  // conv samples (real, imag)

__device__ __forceinline__ void kadd(float& s, float& c, float v) {
    // Kahan compensated add via explicit IEEE intrinsics
    float y = __fadd_rn(v, -c);
    float t = __fadd_rn(s, y);
    c = __fadd_rn(__fadd_rn(t, -s), -y);
    s = t;
}

__device__ __forceinline__ float compute_gx(int j, int seq) {
    // steps = jnp.linspace(0,1,256): steps[j] = fl(j * fl(1/255)), endpoint -> 1.0
    float step255 = __fdiv_rn(1.0f, 255.0f);
    float stepj   = (j == 255) ? 1.0f : __fmul_rn((float)j, step255);
    // end_x = -1 + 2*(seq-1)/2047 ;  x = -1 + step*(end_x+1) ; gx = (x+1)*0.5*2047
    float q    = __fdiv_rn(__fmul_rn(2.0f, (float)(seq - 1)), 2047.0f);
    float endx = __fadd_rn(-1.0f, q);
    float a    = __fadd_rn(endx, 1.0f);
    float xco  = __fadd_rn(-1.0f, __fmul_rn(stepj, a));
    return __fmul_rn(__fmul_rn(__fadd_rn(xco, 1.0f), 0.5f), 2047.0f);
}

// ---------------------------------------------------------------------------
// Kernel 1: per-(b,f) Morlet wavelet table, libdevice fp32 math with the
// reference's exact op ordering; normalized by sum |w| over the full window.
// ---------------------------------------------------------------------------
__global__ void __launch_bounds__(256) k_wavelet(
    const float* __restrict__ fs,
    const float* __restrict__ freqs,
    const float* __restrict__ ncyc)
{
    int bf = blockIdx.x;            // b*32 + f
    int b = bf >> 5, f = bf & 31;
    float fc  = fmaxf(freqs[f], 0.1f);
    float nc  = fmaxf(ncyc[f], 1.0f);
    float fsb = fs[b];
    float omega = __fmul_rn(TWO_PI_F, fc);          // fl(2*pi) * f
    float sigma = __fdiv_rn(nc, omega);             // nc / (2*pi*f)
    float s2    = __fmul_rn(sigma, sigma);
    float d2    = __fmul_rn(2.0f, s2);              // 2*sigma^2

    __shared__ float2 sw[KK];
    __shared__ float sred[256];

    float part = 0.0f;
    for (int k = threadIdx.x; k < KK; k += 256) {
        float t   = (float)(k - HALF);
        float ts  = __fdiv_rn(t, fsb);              // t_sec (fp32)
        float t2  = __fmul_rn(ts, ts);
        float q   = __fdiv_rn(-t2, d2);
        float env = expf(q);                        // libdevice __nv_expf
        float arg = __fmul_rn(omega, ts);
        float cs  = cosf(arg);                      // libdevice (accurate)
        float sn  = sinf(arg);
        float wr = __fmul_rn(cs, env);
        float wi = __fmul_rn(sn, env);
        sw[k] = make_float2(wr, wi);
        part += sqrtf(__fadd_rn(__fmul_rn(wr, wr), __fmul_rn(wi, wi)));
    }
    sred[threadIdx.x] = part;
    __syncthreads();
    for (int o = 128; o > 0; o >>= 1) {
        if (threadIdx.x < o) sred[threadIdx.x] = __fadd_rn(sred[threadIdx.x], sred[threadIdx.x + o]);
        __syncthreads();
    }
    float normv = __fadd_rn(sred[0], 1e-8f);

    float2* dst = g_wav + (size_t)bf * KK;
    for (int k = threadIdx.x; k < KK; k += 256) {
        float2 w = sw[k];
        dst[k] = make_float2(__fdiv_rn(w.x, normv), __fdiv_rn(w.y, normv));
    }
}

// ---------------------------------------------------------------------------
// Kernel 2: sampled convolution. Block = (row-group of 4, channel, batch).
// Thread j computes conv at t0(j) and t0(j)+1 for 4 freq rows. Chunked
// accumulation (plain FFMA within 32-tap chunks) + Kahan merge of chunk sums.
// ---------------------------------------------------------------------------
__global__ void __launch_bounds__(256) k_conv(
    const float* __restrict__ x,
    const float* __restrict__ fs,
    const int*   __restrict__ seq_lens,
    const float* __restrict__ freqs,
    const float* __restrict__ ncyc)
{
    const int g  = blockIdx.x;      // row group 0..7
    const int c  = blockIdx.y;      // channel
    const int b  = blockIdx.z;      // batch
    const int r0 = g * RGROUP;

    __shared__ float xs[TT + 2*HALF + 8];   // zero-padded x row

    const float* xrow = x + ((size_t)b * CC + c) * TT;
    for (int i = threadIdx.x; i < TT + 2*HALF + 8; i += 256) {
        int t = i - HALF;
        xs[i] = (t >= 0 && t < TT) ? xrow[t] : 0.0f;
    }
    __syncthreads();

    // Truncation half-width for this group (largest-sigma row is r0).
    float fc  = fmaxf(freqs[r0], 0.1f);
    float nc  = fmaxf(ncyc[r0], 1.0f);
    float fsb = fs[b];
    float sig_s = nc * fsb / (TWO_PI_F * fc);       // sigma in samples
    int L = (int)(7.0f * sig_s) + 1;                // 7-sigma: dropped mass ~2e-12
    if (L > HALF) L = HALF;

    const int j   = threadIdx.x;
    const int seq = seq_lens[b];
    float gx = compute_gx(j, seq);
    int t0 = (int)floorf(gx);

    // Kahan state: sums + compensations for 4 rows x {r0,i0,r1,i1}
    float sr0[RGROUP], cr0[RGROUP], si0[RGROUP], ci0[RGROUP];
    float sr1[RGROUP], cr1[RGROUP], si1[RGROUP], ci1[RGROUP];
    float wpr[RGROUP], wpi[RGROUP];
    const float2* wp[RGROUP];
#pragma unroll
    for (int r = 0; r < RGROUP; r++) {
        sr0[r]=cr0[r]=si0[r]=ci0[r]=0.0f;
        sr1[r]=cr1[r]=si1[r]=ci1[r]=0.0f;
        wpr[r] = wpi[r] = 0.0f;
        wp[r] = g_wav + (size_t)(b * FF + r0 + r) * KK + HALF;
    }

    const float* xb = xs + HALF + t0;
    const int CHUNK = 32;
    for (int m0 = -L; m0 <= L; m0 += CHUNK) {
        int mend = min(m0 + CHUNK - 1, L);
        float tr0[RGROUP], ti0[RGROUP], tr1[RGROUP], ti1[RGROUP];
#pragma unroll
        for (int r = 0; r < RGROUP; r++) { tr0[r]=ti0[r]=tr1[r]=ti1[r]=0.0f; }
#pragma unroll 4
        for (int m = m0; m <= mend; ++m) {
            float xv = xs[HALF + t0 + m];
#pragma unroll
            for (int r = 0; r < RGROUP; r++) {
                float2 w = __ldg(wp[r] + m);
                tr0[r] += xv * w.x;  ti0[r] += xv * w.y;
                tr1[r] += xv * wpr[r];  ti1[r] += xv * wpi[r];
                wpr[r] = w.x;  wpi[r] = w.y;
            }
        }
#pragma unroll
        for (int r = 0; r < RGROUP; r++) {
            kadd(sr0[r], cr0[r], tr0[r]);
            kadd(si0[r], ci0[r], ti0[r]);
            kadd(sr1[r], cr1[r], tr1[r]);
            kadd(si1[r], ci1[r], ti1[r]);
        }
    }
    {   // epilogue tap (offset +L of the t0+1 output)
        float xv = xb[L + 1];
#pragma unroll
        for (int r = 0; r < RGROUP; r++) {
            kadd(sr1[r], cr1[r], __fmul_rn(xv, wpr[r]));
            kadd(si1[r], ci1[r], __fmul_rn(xv, wpi[r]));
        }
    }

    bool v1 = (t0 + 1) < TT;   // grid_sample zero-padding for x1 == 2048
#pragma unroll
    for (int r = 0; r < RGROUP; r++) {
        int row = r0 + r;
        size_t o = (((size_t)b * FF + row) * CC + c) * PP + 2 * j;
        g_V[o]     = make_float2(sr0[r], si0[r]);
        g_V[o + 1] = v1 ? make_float2(sr1[r], si1[r]) : make_float2(0.0f, 0.0f);
    }
}

// ---------------------------------------------------------------------------
// Kernel 3: bilinear combine + magnitude/phase
// ---------------------------------------------------------------------------
__global__ void __launch_bounds__(256) k_sample(
    const int* __restrict__ seq_lens,
    float* __restrict__ out)
{
    int idx = blockIdx.x * blockDim.x + threadIdx.x;
    if (idx >= BB*CC*FF*JJ) return;
    int j = idx & 255;
    int f = (idx >> 8) & 31;
    int c = (idx >> 13) & 15;
    int b = idx >> 17;

    // y (frequency) coordinate — linspace(-1,1,32): fl(-1 + f*fl(2/31)), endpoint 1.0
    float stepy = __fdiv_rn(2.0f, 31.0f);
    float ylin  = (f == 31) ? 1.0f : __fadd_rn(-1.0f, __fmul_rn((float)f, stepy));
    float gyp   = __fmul_rn(__fmul_rn(__fadd_rn(ylin, 1.0f), 0.5f), 31.0f);
    float y0f   = floorf(gyp);
    float wy1   = __fadd_rn(gyp, -y0f);
    float wy0   = __fadd_rn(1.0f, -wy1);
    int y0 = (int)y0f;
    int y1 = y0 + 1;
    float val1 = (y1 <= FF - 1) ? 1.0f : 0.0f;
    int y1c = min(y1, FF - 1);
    int y0c = min(max(y0, 0), FF - 1);

    // x (time) coordinate — identical code path to k_conv
    int seq = seq_lens[b];
    float gx  = compute_gx(j, seq);
    float x0f = floorf(gx);
    float wx1 = __fadd_rn(gx, -x0f);
    float wx0 = __fadd_rn(1.0f, -wx1);

    int p0 = 2 * j;
    size_t o0 = (((size_t)b * FF + y0c) * CC + c) * PP + p0;
    size_t o1 = (((size_t)b * FF + y1c) * CC + c) * PP + p0;
    float2 v00 = g_V[o0], v01 = g_V[o0 + 1];
    float2 v10 = g_V[o1], v11 = g_V[o1 + 1];

    // reference order: ((g00*w00 + g01*w01) + g10*w10) + g11*w11
    float vr = __fadd_rn(__fadd_rn(__fadd_rn(
                 __fmul_rn(v00.x, __fmul_rn(wy0, wx0)),
                 __fmul_rn(v01.x, __fmul_rn(wy0, wx1))),
                 __fmul_rn(__fmul_rn(v10.x, val1), __fmul_rn(wy1, wx0))),
                 __fmul_rn(__fmul_rn(v11.x, val1), __fmul_rn(wy1, wx1)));
    float vi = __fadd_rn(__fadd_rn(__fadd_rn(
                 __fmul_rn(v00.y, __fmul_rn(wy0, wx0)),
                 __fmul_rn(v01.y, __fmul_rn(wy0, wx1))),
                 __fmul_rn(__fmul_rn(v10.y, val1), __fmul_rn(wy1, wx0))),
                 __fmul_rn(__fmul_rn(v11.y, val1), __fmul_rn(wy1, wx1)));

    float mag = sqrtf(__fadd_rn(__fadd_rn(__fmul_rn(vr, vr), __fmul_rn(vi, vi)), 1e-8f));
    float ph  = __fdiv_rn(atan2f(vi, vr), 3.14159265358979f);

    size_t ob = (((size_t)(b * CC + c) * 2 + 0) * FF + f) * JJ + j;
    out[ob] = mag;
    out[ob + (size_t)FF * JJ] = ph;
}

// ---------------------------------------------------------------------------
extern "C" void kernel_launch(void* const* d_in, const int* in_sizes, int n_in,
                              void* d_out, int out_size)
{
    const float* x        = (const float*)d_in[0];  // (4,16,2048)
    const float* fs       = (const float*)d_in[1];  // (4,)
    const int*   seq_lens = (const int*)  d_in[2];  // (4,)
    const float* freqs    = (const float*)d_in[3];  // (32,)
    const float* ncyc     = (const float*)d_in[4];  // (32,)
    float* out = (float*)d_out;                     // (4,16,2,32,256)

    k_wavelet<<<BB * FF, 256>>>(fs, freqs, ncyc);
    dim3 grid2(NGROUP, CC, BB);
    k_conv<<<grid2, 256>>>(x, fs, seq_lens, freqs, ncyc);
    int total = BB * CC * FF * JJ;
    k_sample<<<(total + 255) / 256, 256>>>(seq_lens, out);
}

// round 4
// speedup vs baseline: 3.5585x; 3.5585x over previous
#include <cuda_runtime.h>

// Problem constants (fixed shapes)
#define BB 4
#define CC 16
#define TT 2048
#define FF 32
#define JJ 256
#define KK 2049          // MAX_T + 1 (odd kernel)
#define HALF 1024
#define PP 512           // 2 time taps per token
#define RGROUP 4
#define NGROUP 8
#define NSLOT 20         // total conv chunks per (b,c)

#define TWO_PI_F 6.28318530717958647692f

typedef unsigned long long ull;

// Scratch (device globals; no allocation allowed)
__device__ ulonglong2 g_wav4[BB*NGROUP*KK*2];       // [b][g][m][2]: 4 rows' (wr,wi), 32B per tap
__device__ float      g_psum[BB*FF*4];              // partial |w| sums (4 sub-blocks per bf)
__device__ float2     g_Vp[(size_t)BB*CC*NSLOT*RGROUP*JJ*2]; // conv chunk partials
__device__ float2     g_V[(size_t)BB*FF*CC*PP];     // reduced conv samples

// Static chunk schedule from worst-case L (fs=500): taps {2049,783,437,303,233,189,159,137}
__constant__ int c_nchunk[NGROUP] = {8,4,2,2,1,1,1,1};
__constant__ int c_cbase [NGROUP] = {0,8,12,14,16,17,18,19};
__constant__ int c_slot_g[NSLOT]  = {0,0,0,0,0,0,0,0, 1,1,1,1, 2,2, 3,3, 4, 5, 6, 7};
__constant__ int c_slot_k[NSLOT]  = {0,1,2,3,4,5,6,7, 0,1,2,3, 0,1, 0,1, 0, 0, 0, 0};

// ---- packed f32x2 helpers -------------------------------------------------
__device__ __forceinline__ ull ffma2(ull a, ull b, ull c) {
    ull d; asm("fma.rn.f32x2 %0, %1, %2, %3;" : "=l"(d) : "l"(a), "l"(b), "l"(c));
    return d;
}
__device__ __forceinline__ ull add2(ull a, ull b) {
    ull d; asm("add.rn.f32x2 %0, %1, %2;" : "=l"(d) : "l"(a), "l"(b));
    return d;
}
__device__ __forceinline__ ull pack2(float v) {
    ull d; asm("mov.b64 %0, {%1, %1};" : "=l"(d) : "f"(v));
    return d;
}
__device__ __forceinline__ float2 unpack2(ull v) {
    float2 r; asm("mov.b64 {%0, %1}, %2;" : "=f"(r.x), "=f"(r.y) : "l"(v));
    return r;
}

__device__ __forceinline__ float compute_gx(int j, int seq) {
    // steps = jnp.linspace(0,1,256): steps[j] = fl(j * fl(1/255)), endpoint -> 1.0
    float step255 = __fdiv_rn(1.0f, 255.0f);
    float stepj   = (j == 255) ? 1.0f : __fmul_rn((float)j, step255);
    float q    = __fdiv_rn(__fmul_rn(2.0f, (float)(seq - 1)), 2047.0f);
    float endx = __fadd_rn(-1.0f, q);
    float a    = __fadd_rn(endx, 1.0f);
    float xco  = __fadd_rn(-1.0f, __fmul_rn(stepj, a));
    return __fmul_rn(__fmul_rn(__fadd_rn(xco, 1.0f), 0.5f), 2047.0f);
}

// ---------------------------------------------------------------------------
// Kernel 1: unnormalized Morlet taps (packed 4-row layout) + partial |w| sums.
// Grid (BB*FF, 4): each sub-block handles 513 taps.
// ---------------------------------------------------------------------------
__global__ void __launch_bounds__(256) k_wavelet(
    const float* __restrict__ fs,
    const float* __restrict__ freqs,
    const float* __restrict__ ncyc)
{
    int bf = blockIdx.x;            // b*32 + f
    int s  = blockIdx.y;            // sub-range 0..3
    int b = bf >> 5, f = bf & 31;
    float fc  = fmaxf(freqs[f], 0.1f);
    float nc  = fmaxf(ncyc[f], 1.0f);
    float fsb = fs[b];
    float omega = __fmul_rn(TWO_PI_F, fc);
    float sigma = __fdiv_rn(nc, omega);
    float d2    = __fmul_rn(2.0f, __fmul_rn(sigma, sigma));

    int k_lo = s * 513;
    int k_hi = min(k_lo + 513, KK);

    __shared__ float sred[256];
    float part = 0.0f;

    int g = f >> 2, r = f & 3;
    float2* wbase = (float2*)&g_wav4[((size_t)(b * NGROUP + g) * KK) * 2];

    for (int k = k_lo + threadIdx.x; k < k_hi; k += 256) {
        float t   = (float)(k - HALF);
        float ts  = __fdiv_rn(t, fsb);
        float t2  = __fmul_rn(ts, ts);
        float q   = __fdiv_rn(-t2, d2);
        float env = expf(q);
        float arg = __fmul_rn(omega, ts);
        float cs  = cosf(arg);
        float sn  = sinf(arg);
        float wr  = __fmul_rn(cs, env);
        float wi  = __fmul_rn(sn, env);
        wbase[k * 4 + r] = make_float2(wr, wi);
        part += sqrtf(__fadd_rn(__fmul_rn(wr, wr), __fmul_rn(wi, wi)));
    }
    sred[threadIdx.x] = part;
    __syncthreads();
    for (int o = 128; o > 0; o >>= 1) {
        if (threadIdx.x < o) sred[threadIdx.x] = __fadd_rn(sred[threadIdx.x], sred[threadIdx.x + o]);
        __syncthreads();
    }
    if (threadIdx.x == 0) g_psum[bf * 4 + s] = sred[0];
}

// ---------------------------------------------------------------------------
// Kernel 2: chunked sampled convolution.
// Block = (chunk slot, channel, batch); thread j = token.
// Each thread: chunk taps x 4 rows x 2 outputs, packed f32x2 accumulation.
// ---------------------------------------------------------------------------
#define CONV_TAP_BODY()                                          \
    {                                                            \
        int a1 = a + 1;                                          \
        float xv1 = xs[a1 + (a1 >> 5)];                          \
        ull p0 = pack2(xv0);                                     \
        ull p1 = pack2(xv1);                                     \
        ulonglong2 wa = wp[0];                                   \
        ulonglong2 wb = wp[1];                                   \
        acc[0] = ffma2(wa.x, p0, acc[0]);                        \
        acc[1] = ffma2(wa.x, p1, acc[1]);                        \
        acc[2] = ffma2(wa.y, p0, acc[2]);                        \
        acc[3] = ffma2(wa.y, p1, acc[3]);                        \
        acc[4] = ffma2(wb.x, p0, acc[4]);                        \
        acc[5] = ffma2(wb.x, p1, acc[5]);                        \
        acc[6] = ffma2(wb.y, p0, acc[6]);                        \
        acc[7] = ffma2(wb.y, p1, acc[7]);                        \
        xv0 = xv1; a = a1; wp += 2;                              \
    }

__global__ void __launch_bounds__(256) k_conv(
    const float* __restrict__ x,
    const float* __restrict__ fs,
    const int*   __restrict__ seq_lens,
    const float* __restrict__ freqs,
    const float* __restrict__ ncyc)
{
    const int slot = blockIdx.x;    // 0..19
    const int c    = blockIdx.y;
    const int b    = blockIdx.z;
    const int g    = c_slot_g[slot];
    const int kk   = c_slot_k[slot];

    // zero-padded, skewed x row: index a in [0,4096], skew a + (a>>5)
    __shared__ float xs[4240];

    const float* xrow = x + ((size_t)b * CC + c) * TT;
    for (int i = threadIdx.x; i < 4097; i += 256) {
        int t = i - HALF;
        float v = (t >= 0 && t < TT) ? xrow[t] : 0.0f;
        xs[i + (i >> 5)] = v;
    }
    __syncthreads();

    // truncation half-width for this group (largest-sigma row = g*4)
    float fc  = fmaxf(freqs[g * RGROUP], 0.1f);
    float nc  = fmaxf(ncyc[g * RGROUP], 1.0f);
    float fsb = fs[b];
    float sig_s = nc * fsb / (TWO_PI_F * fc);
    int L = (int)(7.0f * sig_s) + 1;
    if (L > HALF) L = HALF;

    int taps = 2 * L + 1;
    int ncks = c_nchunk[g];
    int W  = (taps + ncks - 1) / ncks;
    int lo = -L + kk * W;
    int hi = min(lo + W, L + 1);

    const int j   = threadIdx.x;
    const int seq = seq_lens[b];
    float gx = compute_gx(j, seq);
    int t0 = (int)floorf(gx);

    ull sum[8];
#pragma unroll
    for (int i = 0; i < 8; i++) sum[i] = 0ull;

    int a = HALF + t0 + lo;
    const ulonglong2* wp = g_wav4 + ((size_t)(b * NGROUP + g) * KK + (HALF + lo)) * 2;
    float xv0 = (hi > lo) ? xs[a + (a >> 5)] : 0.0f;

    int m = lo;
    // full 32-tap sub-chunks
    for (; m + 32 <= hi; m += 32) {
        ull acc[8];
#pragma unroll
        for (int i = 0; i < 8; i++) acc[i] = 0ull;
#pragma unroll 8
        for (int u = 0; u < 32; ++u) CONV_TAP_BODY();
#pragma unroll
        for (int i = 0; i < 8; i++) sum[i] = add2(sum[i], acc[i]);
    }
    // tail
    if (m < hi) {
        ull acc[8];
#pragma unroll
        for (int i = 0; i < 8; i++) acc[i] = 0ull;
        for (; m < hi; ++m) CONV_TAP_BODY();
#pragma unroll
        for (int i = 0; i < 8; i++) sum[i] = add2(sum[i], acc[i]);
    }

    // store partials: [b][c][slot][r][j][o]
#pragma unroll
    for (int r = 0; r < RGROUP; r++) {
        size_t base = ((((size_t)(b * CC + c) * NSLOT + slot) * RGROUP + r) * JJ + j) * 2;
        g_Vp[base]     = unpack2(sum[r * 2 + 0]);
        g_Vp[base + 1] = unpack2(sum[r * 2 + 1]);
    }
}

// ---------------------------------------------------------------------------
// Kernel 3: reduce chunk partials, apply 1/norm, zero the out-of-range x1 tap.
// ---------------------------------------------------------------------------
__global__ void __launch_bounds__(256) k_red(const int* __restrict__ seq_lens)
{
    int idx = blockIdx.x * 256 + threadIdx.x;   // over BB*FF*CC*JJ
    int j = idx & 255;
    int c = (idx >> 8) & 15;
    int f = (idx >> 12) & 31;
    int b = idx >> 17;
    int g = f >> 2, r = f & 3;

    const float* ps = g_psum + (b * FF + f) * 4;
    float norm = __fadd_rn(__fadd_rn(__fadd_rn(__fadd_rn(ps[0], ps[1]), ps[2]), ps[3]), 1e-8f);

    float2 a0 = make_float2(0.0f, 0.0f);
    float2 a1 = make_float2(0.0f, 0.0f);
    int ncks = c_nchunk[g], cb = c_cbase[g];
    for (int k = 0; k < ncks; ++k) {
        size_t base = ((((size_t)(b * CC + c) * NSLOT + (cb + k)) * RGROUP + r) * JJ + j) * 2;
        float2 v0 = g_Vp[base], v1 = g_Vp[base + 1];
        a0.x = __fadd_rn(a0.x, v0.x);  a0.y = __fadd_rn(a0.y, v0.y);
        a1.x = __fadd_rn(a1.x, v1.x);  a1.y = __fadd_rn(a1.y, v1.y);
    }

    int seq = seq_lens[b];
    float gx = compute_gx(j, seq);
    int t0 = (int)floorf(gx);
    if (t0 + 1 >= TT) a1 = make_float2(0.0f, 0.0f);   // grid_sample zero pad

    size_t o = (((size_t)b * FF + f) * CC + c) * PP + 2 * j;
    g_V[o]     = make_float2(__fdiv_rn(a0.x, norm), __fdiv_rn(a0.y, norm));
    g_V[o + 1] = make_float2(__fdiv_rn(a1.x, norm), __fdiv_rn(a1.y, norm));
}

// ---------------------------------------------------------------------------
// Kernel 4: bilinear combine + magnitude/phase
// ---------------------------------------------------------------------------
__global__ void __launch_bounds__(256) k_sample(
    const int* __restrict__ seq_lens,
    float* __restrict__ out)
{
    int idx = blockIdx.x * blockDim.x + threadIdx.x;
    if (idx >= BB*CC*FF*JJ) return;
    int j = idx & 255;
    int f = (idx >> 8) & 31;
    int c = (idx >> 13) & 15;
    int b = idx >> 17;

    // y (frequency) coordinate — linspace(-1,1,32): fl(-1 + f*fl(2/31)), endpoint 1.0
    float stepy = __fdiv_rn(2.0f, 31.0f);
    float ylin  = (f == 31) ? 1.0f : __fadd_rn(-1.0f, __fmul_rn((float)f, stepy));
    float gyp   = __fmul_rn(__fmul_rn(__fadd_rn(ylin, 1.0f), 0.5f), 31.0f);
    float y0f   = floorf(gyp);
    float wy1   = __fadd_rn(gyp, -y0f);
    float wy0   = __fadd_rn(1.0f, -wy1);
    int y0 = (int)y0f;
    int y1 = y0 + 1;
    float val1 = (y1 <= FF - 1) ? 1.0f : 0.0f;
    int y1c = min(y1, FF - 1);
    int y0c = min(max(y0, 0), FF - 1);

    // x (time) coordinate — identical code path to k_conv/k_red
    int seq = seq_lens[b];
    float gx  = compute_gx(j, seq);
    float x0f = floorf(gx);
    float wx1 = __fadd_rn(gx, -x0f);
    float wx0 = __fadd_rn(1.0f, -wx1);

    int p0 = 2 * j;
    size_t o0 = (((size_t)b * FF + y0c) * CC + c) * PP + p0;
    size_t o1 = (((size_t)b * FF + y1c) * CC + c) * PP + p0;
    float2 v00 = g_V[o0], v01 = g_V[o0 + 1];
    float2 v10 = g_V[o1], v11 = g_V[o1 + 1];

    // reference order: ((g00*w00 + g01*w01) + g10*w10) + g11*w11
    float vr = __fadd_rn(__fadd_rn(__fadd_rn(
                 __fmul_rn(v00.x, __fmul_rn(wy0, wx0)),
                 __fmul_rn(v01.x, __fmul_rn(wy0, wx1))),
                 __fmul_rn(__fmul_rn(v10.x, val1), __fmul_rn(wy1, wx0))),
                 __fmul_rn(__fmul_rn(v11.x, val1), __fmul_rn(wy1, wx1)));
    float vi = __fadd_rn(__fadd_rn(__fadd_rn(
                 __fmul_rn(v00.y, __fmul_rn(wy0, wx0)),
                 __fmul_rn(v01.y, __fmul_rn(wy0, wx1))),
                 __fmul_rn(__fmul_rn(v10.y, val1), __fmul_rn(wy1, wx0))),
                 __fmul_rn(__fmul_rn(v11.y, val1), __fmul_rn(wy1, wx1)));

    float mag = sqrtf(__fadd_rn(__fadd_rn(__fmul_rn(vr, vr), __fmul_rn(vi, vi)), 1e-8f));
    float ph  = __fdiv_rn(atan2f(vi, vr), 3.14159265358979f);

    size_t ob = (((size_t)(b * CC + c) * 2 + 0) * FF + f) * JJ + j;
    out[ob] = mag;
    out[ob + (size_t)FF * JJ] = ph;
}

// ---------------------------------------------------------------------------
extern "C" void kernel_launch(void* const* d_in, const int* in_sizes, int n_in,
                              void* d_out, int out_size)
{
    const float* x        = (const float*)d_in[0];  // (4,16,2048)
    const float* fs       = (const float*)d_in[1];  // (4,)
    const int*   seq_lens = (const int*)  d_in[2];  // (4,)
    const float* freqs    = (const float*)d_in[3];  // (32,)
    const float* ncyc     = (const float*)d_in[4];  // (32,)
    float* out = (float*)d_out;                     // (4,16,2,32,256)

    k_wavelet<<<dim3(BB * FF, 4), 256>>>(fs, freqs, ncyc);
    k_conv<<<dim3(NSLOT, CC, BB), 256>>>(x, fs, seq_lens, freqs, ncyc);
    int total = BB * CC * FF * JJ;
    k_red<<<total / 256, 256>>>(seq_lens);
    k_sample<<<(total + 255) / 256, 256>>>(seq_lens, out);
}

// round 5
// speedup vs baseline: 4.0071x; 1.1261x over previous
#include <cuda_runtime.h>

// Problem constants (fixed shapes)
#define BB 4
#define CC 16
#define TT 2048
#define FF 32
#define JJ 256
#define KK 2049          // MAX_T + 1 (odd kernel)
#define HALF 1024
#define PP 512           // 2 time taps per token
#define RGROUP 4
#define NGROUP 8
#define NSLOT 22         // total conv chunks per (b,c)

#define TWO_PI_F 6.28318530717958647692f

typedef unsigned long long ull;

// Scratch (device globals; no allocation allowed)
__device__ ulonglong2 g_wav4[BB*NGROUP*KK*2];       // [b][g][m][2]: 4 rows' (wr,wi), 32B per tap
__device__ float      g_psum[BB*FF*4];              // partial |w| sums (4 sub-blocks per bf)
__device__ float2     g_Vp[(size_t)BB*CC*NSLOT*RGROUP*JJ*2]; // conv chunk partials

// Static chunk schedule from worst-case L at 6-sigma (fs=500):
// taps {2049,671,373,259,199,161,135,117}
__constant__ int c_nchunk[NGROUP] = {10,4,2,2,1,1,1,1};
__constant__ int c_cbase [NGROUP] = {0,10,14,16,18,19,20,21};
__constant__ int c_slot_g[NSLOT]  = {0,0,0,0,0,0,0,0,0,0, 1,1,1,1, 2,2, 3,3, 4,5,6,7};
__constant__ int c_slot_k[NSLOT]  = {0,1,2,3,4,5,6,7,8,9, 0,1,2,3, 0,1, 0,1, 0,0,0,0};

// ---- packed f32x2 helpers -------------------------------------------------
__device__ __forceinline__ ull ffma2(ull a, ull b, ull c) {
    ull d; asm("fma.rn.f32x2 %0, %1, %2, %3;" : "=l"(d) : "l"(a), "l"(b), "l"(c));
    return d;
}
__device__ __forceinline__ ull add2(ull a, ull b) {
    ull d; asm("add.rn.f32x2 %0, %1, %2;" : "=l"(d) : "l"(a), "l"(b));
    return d;
}
__device__ __forceinline__ ull pack2(float v) {
    ull d; asm("mov.b64 %0, {%1, %1};" : "=l"(d) : "f"(v));
    return d;
}
__device__ __forceinline__ float2 unpack2(ull v) {
    float2 r; asm("mov.b64 {%0, %1}, %2;" : "=f"(r.x), "=f"(r.y) : "l"(v));
    return r;
}

__device__ __forceinline__ float compute_gx(int j, int seq) {
    // steps = jnp.linspace(0,1,256): steps[j] = fl(j * fl(1/255)), endpoint -> 1.0
    float step255 = __fdiv_rn(1.0f, 255.0f);
    float stepj   = (j == 255) ? 1.0f : __fmul_rn((float)j, step255);
    float q    = __fdiv_rn(__fmul_rn(2.0f, (float)(seq - 1)), 2047.0f);
    float endx = __fadd_rn(-1.0f, q);
    float a    = __fadd_rn(endx, 1.0f);
    float xco  = __fadd_rn(-1.0f, __fmul_rn(stepj, a));
    return __fmul_rn(__fmul_rn(__fadd_rn(xco, 1.0f), 0.5f), 2047.0f);
}

// 6-sigma truncation half-width for group g (largest-sigma row = g*4)
__device__ __forceinline__ int group_L(int g, float fsb,
                                       const float* __restrict__ freqs,
                                       const float* __restrict__ ncyc) {
    float fc = fmaxf(freqs[g * RGROUP], 0.1f);
    float nc = fmaxf(ncyc[g * RGROUP], 1.0f);
    float sig = nc * fsb / (TWO_PI_F * fc);   // sigma in samples
    int L = (int)(6.0f * sig) + 1;            // dropped mass ~2e-9
    return min(L, HALF);
}

// ---------------------------------------------------------------------------
// Kernel 1: unnormalized Morlet taps (packed 4-row layout) + partial |w| sums.
// Grid (BB*FF, 4). sin/cos only inside the group's +-(L+2) window; outside,
// |w| == env contributes to the norm directly.
// ---------------------------------------------------------------------------
__global__ void __launch_bounds__(256) k_wavelet(
    const float* __restrict__ fs,
    const float* __restrict__ freqs,
    const float* __restrict__ ncyc)
{
    int bf = blockIdx.x;            // b*32 + f
    int s  = blockIdx.y;            // sub-range 0..3
    int b = bf >> 5, f = bf & 31;
    float fc  = fmaxf(freqs[f], 0.1f);
    float nc  = fmaxf(ncyc[f], 1.0f);
    float fsb = fs[b];
    float omega = __fmul_rn(TWO_PI_F, fc);
    float sigma = __fdiv_rn(nc, omega);
    float d2    = __fmul_rn(2.0f, __fmul_rn(sigma, sigma));

    int g = f >> 2, r = f & 3;
    int Lw = group_L(g, fsb, freqs, ncyc) + 2;   // write window with guard

    int k_lo = s * 513;
    int k_hi = min(k_lo + 513, KK);

    __shared__ float sred[256];
    float part = 0.0f;

    float2* wbase = (float2*)&g_wav4[((size_t)(b * NGROUP + g) * KK) * 2];

    for (int k = k_lo + threadIdx.x; k < k_hi; k += 256) {
        float t   = (float)(k - HALF);
        float ts  = __fdiv_rn(t, fsb);
        float t2  = __fmul_rn(ts, ts);
        float q   = __fdiv_rn(-t2, d2);
        float env = expf(q);
        int m = k - HALF;
        if (m >= -Lw && m <= Lw) {
            float arg = __fmul_rn(omega, ts);
            float cs  = cosf(arg);
            float sn  = sinf(arg);
            float wr  = __fmul_rn(cs, env);
            float wi  = __fmul_rn(sn, env);
            wbase[k * 4 + r] = make_float2(wr, wi);
            part += sqrtf(__fadd_rn(__fmul_rn(wr, wr), __fmul_rn(wi, wi)));
        } else {
            part += env;   // |w| = env outside the window (dev ~1e-15 of norm)
        }
    }
    sred[threadIdx.x] = part;
    __syncthreads();
    for (int o = 128; o > 0; o >>= 1) {
        if (threadIdx.x < o) sred[threadIdx.x] = __fadd_rn(sred[threadIdx.x], sred[threadIdx.x + o]);
        __syncthreads();
    }
    if (threadIdx.x == 0) g_psum[bf * 4 + s] = sred[0];
}

// ---------------------------------------------------------------------------
// Kernel 2: chunked sampled convolution (packed f32x2 accumulation).
// ---------------------------------------------------------------------------
#define CONV_TAP_BODY()                                          \
    {                                                            \
        int a1 = a + 1;                                          \
        float xv1 = xs[a1 + (a1 >> 5)];                          \
        ull p0 = pack2(xv0);                                     \
        ull p1 = pack2(xv1);                                     \
        ulonglong2 wa = wp[0];                                   \
        ulonglong2 wb = wp[1];                                   \
        acc[0] = ffma2(wa.x, p0, acc[0]);                        \
        acc[1] = ffma2(wa.x, p1, acc[1]);                        \
        acc[2] = ffma2(wa.y, p0, acc[2]);                        \
        acc[3] = ffma2(wa.y, p1, acc[3]);                        \
        acc[4] = ffma2(wb.x, p0, acc[4]);                        \
        acc[5] = ffma2(wb.x, p1, acc[5]);                        \
        acc[6] = ffma2(wb.y, p0, acc[6]);                        \
        acc[7] = ffma2(wb.y, p1, acc[7]);                        \
        xv0 = xv1; a = a1; wp += 2;                              \
    }

__global__ void __launch_bounds__(256) k_conv(
    const float* __restrict__ x,
    const float* __restrict__ fs,
    const int*   __restrict__ seq_lens,
    const float* __restrict__ freqs,
    const float* __restrict__ ncyc)
{
    const int slot = blockIdx.x;    // 0..21
    const int c    = blockIdx.y;
    const int b    = blockIdx.z;
    const int g    = c_slot_g[slot];
    const int kk   = c_slot_k[slot];

    // zero-padded, skewed x row: index a in [0,4096], skew a + (a>>5)
    __shared__ float xs[4240];

    const float fsb = fs[b];
    int L = group_L(g, fsb, freqs, ncyc);

    // ---- prologue: fill only [HALF-L, HALF+2048+L] ----
    const float4* xrow4 = (const float4*)(x + ((size_t)b * CC + c) * TT);
    // data region [HALF, HALF+2047], vectorized
    for (int t4 = threadIdx.x; t4 < TT / 4; t4 += 256) {
        float4 v = xrow4[t4];
        int i0 = HALF + 4 * t4;
        xs[(i0    ) + ((i0    ) >> 5)] = v.x;
        xs[(i0 + 1) + ((i0 + 1) >> 5)] = v.y;
        xs[(i0 + 2) + ((i0 + 2) >> 5)] = v.z;
        xs[(i0 + 3) + ((i0 + 3) >> 5)] = v.w;
    }
    // zero pads
    for (int d = threadIdx.x; d < L; d += 256) {
        int il = HALF - 1 - d;
        xs[il + (il >> 5)] = 0.0f;
        int ir = HALF + TT + d;
        xs[ir + (ir >> 5)] = 0.0f;
    }
    if (threadIdx.x == 0) {          // index HALF+2048+L (read by last xv1)
        int ie = HALF + TT + L;
        xs[ie + (ie >> 5)] = 0.0f;
    }
    __syncthreads();

    int taps = 2 * L + 1;
    int ncks = c_nchunk[g];
    int W  = (taps + ncks - 1) / ncks;
    int lo = -L + kk * W;
    int hi = min(lo + W, L + 1);

    const int j   = threadIdx.x;
    const int seq = seq_lens[b];
    float gx = compute_gx(j, seq);
    int t0 = (int)floorf(gx);

    ull sum[8];
#pragma unroll
    for (int i = 0; i < 8; i++) sum[i] = 0ull;

    int a = HALF + t0 + lo;
    const ulonglong2* wp = g_wav4 + ((size_t)(b * NGROUP + g) * KK + (HALF + lo)) * 2;
    float xv0 = (hi > lo) ? xs[a + (a >> 5)] : 0.0f;

    int m = lo;
    for (; m + 32 <= hi; m += 32) {
        ull acc[8];
#pragma unroll
        for (int i = 0; i < 8; i++) acc[i] = 0ull;
#pragma unroll 8
        for (int u = 0; u < 32; ++u) CONV_TAP_BODY();
#pragma unroll
        for (int i = 0; i < 8; i++) sum[i] = add2(sum[i], acc[i]);
    }
    if (m < hi) {
        ull acc[8];
#pragma unroll
        for (int i = 0; i < 8; i++) acc[i] = 0ull;
        for (; m < hi; ++m) CONV_TAP_BODY();
#pragma unroll
        for (int i = 0; i < 8; i++) sum[i] = add2(sum[i], acc[i]);
    }

    // store partials: [b][c][slot][r][j][o]
#pragma unroll
    for (int r = 0; r < RGROUP; r++) {
        size_t base = ((((size_t)(b * CC + c) * NSLOT + slot) * RGROUP + r) * JJ + j) * 2;
        g_Vp[base]     = unpack2(sum[r * 2 + 0]);
        g_Vp[base + 1] = unpack2(sum[r * 2 + 1]);
    }
}

// ---------------------------------------------------------------------------
// Kernel 3 (fused): reduce chunk partials for the two bilinear rows, apply
// 1/norm, zero the out-of-range x1 tap, bilinear combine, magnitude/phase.
// Bit-identical op order to the previous k_red + k_sample pair.
// ---------------------------------------------------------------------------
__device__ __forceinline__ void reduce_row(
    int b, int c, int row, int j, int zero_x1, float2& a0, float2& a1)
{
    int g = row >> 2, r = row & 3;
    const float* ps = g_psum + (b * FF + row) * 4;
    float norm = __fadd_rn(__fadd_rn(__fadd_rn(__fadd_rn(ps[0], ps[1]), ps[2]), ps[3]), 1e-8f);

    float2 s0 = make_float2(0.0f, 0.0f);
    float2 s1 = make_float2(0.0f, 0.0f);
    int ncks = c_nchunk[g], cb = c_cbase[g];
    for (int k = 0; k < ncks; ++k) {
        size_t base = ((((size_t)(b * CC + c) * NSLOT + (cb + k)) * RGROUP + r) * JJ + j) * 2;
        float2 v0 = g_Vp[base], v1 = g_Vp[base + 1];
        s0.x = __fadd_rn(s0.x, v0.x);  s0.y = __fadd_rn(s0.y, v0.y);
        s1.x = __fadd_rn(s1.x, v1.x);  s1.y = __fadd_rn(s1.y, v1.y);
    }
    if (zero_x1) s1 = make_float2(0.0f, 0.0f);
    a0 = make_float2(__fdiv_rn(s0.x, norm), __fdiv_rn(s0.y, norm));
    a1 = make_float2(__fdiv_rn(s1.x, norm), __fdiv_rn(s1.y, norm));
}

__global__ void __launch_bounds__(256) k_out(
    const int* __restrict__ seq_lens,
    float* __restrict__ out)
{
    int idx = blockIdx.x * blockDim.x + threadIdx.x;   // ((b*CC+c)*FF+f)*JJ+j
    if (idx >= BB*CC*FF*JJ) return;
    int j = idx & 255;
    int f = (idx >> 8) & 31;
    int c = (idx >> 13) & 15;
    int b = idx >> 17;

    // y (frequency) coordinate — linspace(-1,1,32): fl(-1 + f*fl(2/31)), endpoint 1.0
    float stepy = __fdiv_rn(2.0f, 31.0f);
    float ylin  = (f == 31) ? 1.0f : __fadd_rn(-1.0f, __fmul_rn((float)f, stepy));
    float gyp   = __fmul_rn(__fmul_rn(__fadd_rn(ylin, 1.0f), 0.5f), 31.0f);
    float y0f   = floorf(gyp);
    float wy1   = __fadd_rn(gyp, -y0f);
    float wy0   = __fadd_rn(1.0f, -wy1);
    int y0 = (int)y0f;
    int y1 = y0 + 1;
    float val1 = (y1 <= FF - 1) ? 1.0f : 0.0f;
    int y1c = min(y1, FF - 1);
    int y0c = min(max(y0, 0), FF - 1);

    // x (time) coordinate — identical code path to k_conv
    int seq = seq_lens[b];
    float gx  = compute_gx(j, seq);
    float x0f = floorf(gx);
    float wx1 = __fadd_rn(gx, -x0f);
    float wx0 = __fadd_rn(1.0f, -wx1);
    int t0 = (int)x0f;
    int zero_x1 = (t0 + 1 >= TT);   // grid_sample zero pad

    float2 v00, v01, v10, v11;
    reduce_row(b, c, y0c, j, zero_x1, v00, v01);
    reduce_row(b, c, y1c, j, zero_x1, v10, v11);

    // reference order: ((g00*w00 + g01*w01) + g10*w10) + g11*w11
    float vr = __fadd_rn(__fadd_rn(__fadd_rn(
                 __fmul_rn(v00.x, __fmul_rn(wy0, wx0)),
                 __fmul_rn(v01.x, __fmul_rn(wy0, wx1))),
                 __fmul_rn(__fmul_rn(v10.x, val1), __fmul_rn(wy1, wx0))),
                 __fmul_rn(__fmul_rn(v11.x, val1), __fmul_rn(wy1, wx1)));
    float vi = __fadd_rn(__fadd_rn(__fadd_rn(
                 __fmul_rn(v00.y, __fmul_rn(wy0, wx0)),
                 __fmul_rn(v01.y, __fmul_rn(wy0, wx1))),
                 __fmul_rn(__fmul_rn(v10.y, val1), __fmul_rn(wy1, wx0))),
                 __fmul_rn(__fmul_rn(v11.y, val1), __fmul_rn(wy1, wx1)));

    float mag = sqrtf(__fadd_rn(__fadd_rn(__fmul_rn(vr, vr), __fmul_rn(vi, vi)), 1e-8f));
    float ph  = __fdiv_rn(atan2f(vi, vr), 3.14159265358979f);

    size_t ob = (((size_t)(b * CC + c) * 2 + 0) * FF + f) * JJ + j;
    out[ob] = mag;
    out[ob + (size_t)FF * JJ] = ph;
}

// ---------------------------------------------------------------------------
extern "C" void kernel_launch(void* const* d_in, const int* in_sizes, int n_in,
                              void* d_out, int out_size)
{
    const float* x        = (const float*)d_in[0];  // (4,16,2048)
    const float* fs       = (const float*)d_in[1];  // (4,)
    const int*   seq_lens = (const int*)  d_in[2];  // (4,)
    const float* freqs    = (const float*)d_in[3];  // (32,)
    const float* ncyc     = (const float*)d_in[4];  // (32,)
    float* out = (float*)d_out;                     // (4,16,2,32,256)

    k_wavelet<<<dim3(BB * FF, 4), 256>>>(fs, freqs, ncyc);
    k_conv<<<dim3(NSLOT, CC, BB), 256>>>(x, fs, seq_lens, freqs, ncyc);
    int total = BB * CC * FF * JJ;
    k_out<<<(total + 255) / 256, 256>>>(seq_lens, out);
}

// round 6
// speedup vs baseline: 5.5098x; 1.3750x over previous
#include <cuda_runtime.h>

// Problem constants (fixed shapes)
#define BB 4
#define CC 16
#define TT 2048
#define FF 32
#define JJ 256
#define KK 2049          // MAX_T + 1 (odd kernel)
#define HALF 1024
#define PP 512           // 2 time taps per token
#define RGROUP 4
#define NGROUP 8
#define NSLOT 22         // total conv chunks per (b,c)
#define MAXCHUNK 208     // max taps per chunk (g0 worst: ceil(2049/10)=205)

#define TWO_PI_F 6.28318530717958647692f

typedef unsigned long long ull;

// Scratch (device globals; no allocation allowed)
__device__ ulonglong2 g_wav4[BB*NGROUP*KK*2];       // [b][g][m][2]: 4 rows' (wr,wi), 32B per tap
__device__ float      g_psum[BB*FF*4];              // partial |w| sums (4 sub-blocks per bf)
__device__ float2     g_Vp[(size_t)BB*CC*NSLOT*RGROUP*JJ*2]; // conv chunk partials

// Static chunk schedule from worst-case L at 6-sigma (fs=500):
// taps {2049,671,373,259,199,161,135,117}
__constant__ int c_nchunk[NGROUP] = {10,4,2,2,1,1,1,1};
__constant__ int c_cbase [NGROUP] = {0,10,14,16,18,19,20,21};
__constant__ int c_slot_g[NSLOT]  = {0,0,0,0,0,0,0,0,0,0, 1,1,1,1, 2,2, 3,3, 4,5,6,7};
__constant__ int c_slot_k[NSLOT]  = {0,1,2,3,4,5,6,7,8,9, 0,1,2,3, 0,1, 0,1, 0,0,0,0};

// ---- packed f32x2 helpers -------------------------------------------------
__device__ __forceinline__ ull ffma2(ull a, ull b, ull c) {
    ull d; asm("fma.rn.f32x2 %0, %1, %2, %3;" : "=l"(d) : "l"(a), "l"(b), "l"(c));
    return d;
}
__device__ __forceinline__ ull add2(ull a, ull b) {
    ull d; asm("add.rn.f32x2 %0, %1, %2;" : "=l"(d) : "l"(a), "l"(b));
    return d;
}
__device__ __forceinline__ ull pack2(float v) {
    ull d; asm("mov.b64 %0, {%1, %1};" : "=l"(d) : "f"(v));
    return d;
}
__device__ __forceinline__ float2 unpack2(ull v) {
    float2 r; asm("mov.b64 {%0, %1}, %2;" : "=f"(r.x), "=f"(r.y) : "l"(v));
    return r;
}

__device__ __forceinline__ float compute_gx(int j, int seq) {
    // steps = jnp.linspace(0,1,256): steps[j] = fl(j * fl(1/255)), endpoint -> 1.0
    float step255 = __fdiv_rn(1.0f, 255.0f);
    float stepj   = (j == 255) ? 1.0f : __fmul_rn((float)j, step255);
    float q    = __fdiv_rn(__fmul_rn(2.0f, (float)(seq - 1)), 2047.0f);
    float endx = __fadd_rn(-1.0f, q);
    float a    = __fadd_rn(endx, 1.0f);
    float xco  = __fadd_rn(-1.0f, __fmul_rn(stepj, a));
    return __fmul_rn(__fmul_rn(__fadd_rn(xco, 1.0f), 0.5f), 2047.0f);
}

// 6-sigma truncation half-width for group g (largest-sigma row = g*4)
__device__ __forceinline__ int group_L(int g, float fsb,
                                       const float* __restrict__ freqs,
                                       const float* __restrict__ ncyc) {
    float fc = fmaxf(freqs[g * RGROUP], 0.1f);
    float nc = fmaxf(ncyc[g * RGROUP], 1.0f);
    float sig = nc * fsb / (TWO_PI_F * fc);   // sigma in samples
    int L = (int)(6.0f * sig) + 1;            // dropped mass ~2e-9
    return min(L, HALF);
}

// ---------------------------------------------------------------------------
// Kernel 1: unnormalized Morlet taps (packed 4-row layout) + partial |w| sums.
// ---------------------------------------------------------------------------
__global__ void __launch_bounds__(256) k_wavelet(
    const float* __restrict__ fs,
    const float* __restrict__ freqs,
    const float* __restrict__ ncyc)
{
    int bf = blockIdx.x;            // b*32 + f
    int s  = blockIdx.y;            // sub-range 0..3
    int b = bf >> 5, f = bf & 31;
    float fc  = fmaxf(freqs[f], 0.1f);
    float nc  = fmaxf(ncyc[f], 1.0f);
    float fsb = fs[b];
    float omega = __fmul_rn(TWO_PI_F, fc);
    float sigma = __fdiv_rn(nc, omega);
    float d2    = __fmul_rn(2.0f, __fmul_rn(sigma, sigma));

    int g = f >> 2, r = f & 3;
    int Lw = group_L(g, fsb, freqs, ncyc) + 2;   // write window with guard

    int k_lo = s * 513;
    int k_hi = min(k_lo + 513, KK);

    __shared__ float sred[256];
    float part = 0.0f;

    float2* wbase = (float2*)&g_wav4[((size_t)(b * NGROUP + g) * KK) * 2];

    for (int k = k_lo + threadIdx.x; k < k_hi; k += 256) {
        float t   = (float)(k - HALF);
        float ts  = __fdiv_rn(t, fsb);
        float t2  = __fmul_rn(ts, ts);
        float q   = __fdiv_rn(-t2, d2);
        float env = expf(q);
        int m = k - HALF;
        if (m >= -Lw && m <= Lw) {
            float arg = __fmul_rn(omega, ts);
            float cs  = cosf(arg);
            float sn  = sinf(arg);
            float wr  = __fmul_rn(cs, env);
            float wi  = __fmul_rn(sn, env);
            wbase[k * 4 + r] = make_float2(wr, wi);
            part += sqrtf(__fadd_rn(__fmul_rn(wr, wr), __fmul_rn(wi, wi)));
        } else {
            part += env;   // |w| = env outside the window (dev ~1e-15 of norm)
        }
    }
    sred[threadIdx.x] = part;
    __syncthreads();
    for (int o = 128; o > 0; o >>= 1) {
        if (threadIdx.x < o) sred[threadIdx.x] = __fadd_rn(sred[threadIdx.x], sred[threadIdx.x + o]);
        __syncthreads();
    }
    if (threadIdx.x == 0) g_psum[bf * 4 + s] = sred[0];
}

// ---------------------------------------------------------------------------
// Kernel 2: chunked sampled convolution (packed f32x2 accumulation).
// Weight chunk staged in smem; x row in smem with a>>3 skew (conflict-free
// for the 4..8-float token strides).
// ---------------------------------------------------------------------------
#define SKEW(a) ((a) + ((a) >> 3))

#define CONV_TAP_BODY()                                          \
    {                                                            \
        int a1 = a + 1;                                          \
        float xv1 = xs[SKEW(a1)];                                \
        ull p0 = pack2(xv0);                                     \
        ull p1 = pack2(xv1);                                     \
        ulonglong2 wa = wsp[0];                                  \
        ulonglong2 wb = wsp[1];                                  \
        acc[0] = ffma2(wa.x, p0, acc[0]);                        \
        acc[1] = ffma2(wa.x, p1, acc[1]);                        \
        acc[2] = ffma2(wa.y, p0, acc[2]);                        \
        acc[3] = ffma2(wa.y, p1, acc[3]);                        \
        acc[4] = ffma2(wb.x, p0, acc[4]);                        \
        acc[5] = ffma2(wb.x, p1, acc[5]);                        \
        acc[6] = ffma2(wb.y, p0, acc[6]);                        \
        acc[7] = ffma2(wb.y, p1, acc[7]);                        \
        xv0 = xv1; a = a1; wsp += 2;                             \
    }

__global__ void __launch_bounds__(256) k_conv(
    const float* __restrict__ x,
    const float* __restrict__ fs,
    const int*   __restrict__ seq_lens,
    const float* __restrict__ freqs,
    const float* __restrict__ ncyc)
{
    const int slot = blockIdx.x;    // 0..21
    const int c    = blockIdx.y;
    const int b    = blockIdx.z;
    const int g    = c_slot_g[slot];
    const int kk   = c_slot_k[slot];

    // zero-padded, skewed x row: index a in [0,4096], skew a + (a>>3)
    __shared__ float      xs[4620];
    __shared__ ulonglong2 ws[2 * MAXCHUNK];   // staged weight chunk (32B/tap)

    const float fsb = fs[b];
    int L = group_L(g, fsb, freqs, ncyc);

    int taps = 2 * L + 1;
    int ncks = c_nchunk[g];
    int W  = (taps + ncks - 1) / ncks;
    int lo = -L + kk * W;
    int hi = min(lo + W, L + 1);
    int clen = hi - lo;                      // <= MAXCHUNK

    // ---- stage weight chunk: g_wav4[(b,g, HALF+lo ... ) * 2] ----
    {
        const float4* src = (const float4*)(g_wav4 + ((size_t)(b * NGROUP + g) * KK + (HALF + lo)) * 2);
        float4* dst = (float4*)ws;
        int n4 = clen * 2;                   // float4s to copy
        for (int i = threadIdx.x; i < n4; i += 256) dst[i] = src[i];
    }

    // ---- x prologue: fill data + pads [HALF-L, HALF+2048+L] ----
    const float4* xrow4 = (const float4*)(x + ((size_t)b * CC + c) * TT);
    for (int t4 = threadIdx.x; t4 < TT / 4; t4 += 256) {
        float4 v = xrow4[t4];
        int i0 = HALF + 4 * t4;
        xs[SKEW(i0    )] = v.x;
        xs[SKEW(i0 + 1)] = v.y;
        xs[SKEW(i0 + 2)] = v.z;
        xs[SKEW(i0 + 3)] = v.w;
    }
    for (int d = threadIdx.x; d < L; d += 256) {
        int il = HALF - 1 - d;
        xs[SKEW(il)] = 0.0f;
        int ir = HALF + TT + d;
        xs[SKEW(ir)] = 0.0f;
    }
    if (threadIdx.x == 0) {                  // index HALF+2048+L (last xv1)
        int ie = HALF + TT + L;
        xs[SKEW(ie)] = 0.0f;
    }
    __syncthreads();

    const int j   = threadIdx.x;
    const int seq = seq_lens[b];
    float gx = compute_gx(j, seq);
    int t0 = (int)floorf(gx);

    ull sum[8];
#pragma unroll
    for (int i = 0; i < 8; i++) sum[i] = 0ull;

    int a = HALF + t0 + lo;
    const ulonglong2* wsp = ws;
    float xv0 = (clen > 0) ? xs[SKEW(a)] : 0.0f;

    int m = lo;
    for (; m + 32 <= hi; m += 32) {
        ull acc[8];
#pragma unroll
        for (int i = 0; i < 8; i++) acc[i] = 0ull;
#pragma unroll 8
        for (int u = 0; u < 32; ++u) CONV_TAP_BODY();
#pragma unroll
        for (int i = 0; i < 8; i++) sum[i] = add2(sum[i], acc[i]);
    }
    if (m < hi) {
        ull acc[8];
#pragma unroll
        for (int i = 0; i < 8; i++) acc[i] = 0ull;
        for (; m < hi; ++m) CONV_TAP_BODY();
#pragma unroll
        for (int i = 0; i < 8; i++) sum[i] = add2(sum[i], acc[i]);
    }

    // store partials: [b][c][slot][r][j][o]
#pragma unroll
    for (int r = 0; r < RGROUP; r++) {
        size_t base = ((((size_t)(b * CC + c) * NSLOT + slot) * RGROUP + r) * JJ + j) * 2;
        g_Vp[base]     = unpack2(sum[r * 2 + 0]);
        g_Vp[base + 1] = unpack2(sum[r * 2 + 1]);
    }
}

// ---------------------------------------------------------------------------
// Kernel 3 (fused): reduce chunk partials for the two bilinear rows, apply
// 1/norm, zero the out-of-range x1 tap, bilinear combine, magnitude/phase.
// ---------------------------------------------------------------------------
__device__ __forceinline__ void reduce_row(
    int b, int c, int row, int j, int zero_x1, float2& a0, float2& a1)
{
    int g = row >> 2, r = row & 3;
    const float* ps = g_psum + (b * FF + row) * 4;
    float norm = __fadd_rn(__fadd_rn(__fadd_rn(__fadd_rn(ps[0], ps[1]), ps[2]), ps[3]), 1e-8f);

    float2 s0 = make_float2(0.0f, 0.0f);
    float2 s1 = make_float2(0.0f, 0.0f);
    int ncks = c_nchunk[g], cb = c_cbase[g];
    for (int k = 0; k < ncks; ++k) {
        size_t base = ((((size_t)(b * CC + c) * NSLOT + (cb + k)) * RGROUP + r) * JJ + j) * 2;
        float2 v0 = g_Vp[base], v1 = g_Vp[base + 1];
        s0.x = __fadd_rn(s0.x, v0.x);  s0.y = __fadd_rn(s0.y, v0.y);
        s1.x = __fadd_rn(s1.x, v1.x);  s1.y = __fadd_rn(s1.y, v1.y);
    }
    if (zero_x1) s1 = make_float2(0.0f, 0.0f);
    a0 = make_float2(__fdiv_rn(s0.x, norm), __fdiv_rn(s0.y, norm));
    a1 = make_float2(__fdiv_rn(s1.x, norm), __fdiv_rn(s1.y, norm));
}

__global__ void __launch_bounds__(256) k_out(
    const int* __restrict__ seq_lens,
    float* __restrict__ out)
{
    int idx = blockIdx.x * blockDim.x + threadIdx.x;   // ((b*CC+c)*FF+f)*JJ+j
    if (idx >= BB*CC*FF*JJ) return;
    int j = idx & 255;
    int f = (idx >> 8) & 31;
    int c = (idx >> 13) & 15;
    int b = idx >> 17;

    // y (frequency) coordinate — linspace(-1,1,32): fl(-1 + f*fl(2/31)), endpoint 1.0
    float stepy = __fdiv_rn(2.0f, 31.0f);
    float ylin  = (f == 31) ? 1.0f : __fadd_rn(-1.0f, __fmul_rn((float)f, stepy));
    float gyp   = __fmul_rn(__fmul_rn(__fadd_rn(ylin, 1.0f), 0.5f), 31.0f);
    float y0f   = floorf(gyp);
    float wy1   = __fadd_rn(gyp, -y0f);
    float wy0   = __fadd_rn(1.0f, -wy1);
    int y0 = (int)y0f;
    int y1 = y0 + 1;
    float val1 = (y1 <= FF - 1) ? 1.0f : 0.0f;
    int y1c = min(y1, FF - 1);
    int y0c = min(max(y0, 0), FF - 1);

    // x (time) coordinate — identical code path to k_conv
    int seq = seq_lens[b];
    float gx  = compute_gx(j, seq);
    float x0f = floorf(gx);
    float wx1 = __fadd_rn(gx, -x0f);
    float wx0 = __fadd_rn(1.0f, -wx1);
    int t0 = (int)x0f;
    int zero_x1 = (t0 + 1 >= TT);   // grid_sample zero pad

    float2 v00, v01, v10, v11;
    reduce_row(b, c, y0c, j, zero_x1, v00, v01);
    reduce_row(b, c, y1c, j, zero_x1, v10, v11);

    // reference order: ((g00*w00 + g01*w01) + g10*w10) + g11*w11
    float vr = __fadd_rn(__fadd_rn(__fadd_rn(
                 __fmul_rn(v00.x, __fmul_rn(wy0, wx0)),
                 __fmul_rn(v01.x, __fmul_rn(wy0, wx1))),
                 __fmul_rn(__fmul_rn(v10.x, val1), __fmul_rn(wy1, wx0))),
                 __fmul_rn(__fmul_rn(v11.x, val1), __fmul_rn(wy1, wx1)));
    float vi = __fadd_rn(__fadd_rn(__fadd_rn(
                 __fmul_rn(v00.y, __fmul_rn(wy0, wx0)),
                 __fmul_rn(v01.y, __fmul_rn(wy0, wx1))),
                 __fmul_rn(__fmul_rn(v10.y, val1), __fmul_rn(wy1, wx0))),
                 __fmul_rn(__fmul_rn(v11.y, val1), __fmul_rn(wy1, wx1)));

    float mag = sqrtf(__fadd_rn(__fadd_rn(__fmul_rn(vr, vr), __fmul_rn(vi, vi)), 1e-8f));
    float ph  = __fdiv_rn(atan2f(vi, vr), 3.14159265358979f);

    size_t ob = (((size_t)(b * CC + c) * 2 + 0) * FF + f) * JJ + j;
    out[ob] = mag;
    out[ob + (size_t)FF * JJ] = ph;
}

// ---------------------------------------------------------------------------
extern "C" void kernel_launch(void* const* d_in, const int* in_sizes, int n_in,
                              void* d_out, int out_size)
{
    const float* x        = (const float*)d_in[0];  // (4,16,2048)
    const float* fs       = (const float*)d_in[1];  // (4,)
    const int*   seq_lens = (const int*)  d_in[2];  // (4,)
    const float* freqs    = (const float*)d_in[3];  // (32,)
    const float* ncyc     = (const float*)d_in[4];  // (32,)
    float* out = (float*)d_out;                     // (4,16,2,32,256)

    k_wavelet<<<dim3(BB * FF, 4), 256>>>(fs, freqs, ncyc);
    k_conv<<<dim3(NSLOT, CC, BB), 256>>>(x, fs, seq_lens, freqs, ncyc);
    int total = BB * CC * FF * JJ;
    k_out<<<(total + 255) / 256, 256>>>(seq_lens, out);
}

// round 13
// speedup vs baseline: 5.5757x; 1.0120x over previous
#include <cuda_runtime.h>

// Problem constants (fixed shapes)
#define BB 4
#define CC 16
#define TT 2048
#define FF 32
#define JJ 256
#define KK 2049          // MAX_T + 1 (odd kernel)
#define HALF 1024
#define PP 512           // 2 time taps per token
#define RGROUP 4
#define NGROUP 8
#define NSLOT 22         // total conv chunks per (b,c)
#define MAXCHUNK 208     // max taps per chunk (g0 worst: ceil(2049/10)=205)
#define NW 8             // wavelet norm sub-blocks
#define BUFOFF 4

#define TWO_PI_F 6.28318530717958647692f
#define PI_F     3.14159265358979f
#define PI_2_F   1.57079632679490f

typedef unsigned long long ull;

// Scratch (device globals; no allocation allowed)
__device__ ulonglong2 g_wav4[BB*NGROUP*KK*2];       // [b][g][m][2]: 4 rows' (wr,wi), 32B/tap
__device__ float      g_psum[BB*FF*NW];             // partial |w| sums
__device__ float4     g_Vp[(size_t)BB*CC*NSLOT*RGROUP*JJ]; // conv chunk partials (v0,v1)

// Static chunk schedule from worst-case L at 6-sigma (fs=500):
// taps {2049,671,373,259,199,161,135,117}
__constant__ int c_nchunk[NGROUP] = {10,4,2,2,1,1,1,1};
__constant__ int c_cbase [NGROUP] = {0,10,14,16,18,19,20,21};
__constant__ int c_slot_g[NSLOT]  = {0,0,0,0,0,0,0,0,0,0, 1,1,1,1, 2,2, 3,3, 4,5,6,7};
__constant__ int c_slot_k[NSLOT]  = {0,1,2,3,4,5,6,7,8,9, 0,1,2,3, 0,1, 0,1, 0,0,0,0};

// ---- packed f32x2 helpers -------------------------------------------------
__device__ __forceinline__ ull ffma2(ull a, ull b, ull c) {
    ull d; asm("fma.rn.f32x2 %0, %1, %2, %3;" : "=l"(d) : "l"(a), "l"(b), "l"(c));
    return d;
}
__device__ __forceinline__ ull pack2(float v) {
    ull d; asm("mov.b64 %0, {%1, %1};" : "=l"(d) : "f"(v));
    return d;
}
__device__ __forceinline__ float2 unpack2(ull v) {
    float2 r; asm("mov.b64 {%0, %1}, %2;" : "=f"(r.x), "=f"(r.y) : "l"(v));
    return r;
}

__device__ __forceinline__ float compute_gx(int j, int seq) {
    // steps = jnp.linspace(0,1,256): steps[j] = fl(j * fl(1/255)), endpoint -> 1.0
    float step255 = __fdiv_rn(1.0f, 255.0f);
    float stepj   = (j == 255) ? 1.0f : __fmul_rn((float)j, step255);
    float q    = __fdiv_rn(__fmul_rn(2.0f, (float)(seq - 1)), 2047.0f);
    float endx = __fadd_rn(-1.0f, q);
    float a    = __fadd_rn(endx, 1.0f);
    float xco  = __fadd_rn(-1.0f, __fmul_rn(stepj, a));
    return __fmul_rn(__fmul_rn(__fadd_rn(xco, 1.0f), 0.5f), 2047.0f);
}

// 6-sigma truncation half-width for group g (largest-sigma row = g*4)
__device__ __forceinline__ int group_L(int g, float fsb,
                                       const float* __restrict__ freqs,
                                       const float* __restrict__ ncyc) {
    float fc = fmaxf(freqs[g * RGROUP], 0.1f);
    float nc = fmaxf(ncyc[g * RGROUP], 1.0f);
    float sig = nc * fsb / (TWO_PI_F * fc);   // sigma in samples
    int L = (int)(6.0f * sig) + 1;            // dropped mass ~2e-9
    return min(L, HALF);
}

// A&S 4.4.49 atan poly on [0,1] (abs err ~2e-8) -> atan2
__device__ __forceinline__ float fast_atan2(float y, float x) {
    float ax = fabsf(x), ay = fabsf(y);
    float mx = fmaxf(ax, ay), mn = fminf(ax, ay);
    float z  = __fdiv_rn(mn, mx);     // NaN if both 0 (fixed below)
    float t  = z * z;
    float p  = -0.0161657367f + t * 0.0028662257f;
    p = fmaf(p, t,  0.0429096138f);
    p = fmaf(p, t, -0.0752896400f);
    p = fmaf(p, t,  0.1065626393f);
    p = fmaf(p, t, -0.1420889944f);
    p = fmaf(p, t,  0.1999355085f);
    p = fmaf(p, t, -0.3333314528f);
    p = fmaf(p, t,  1.0f);
    p = p * z;
    if (ay > ax)   p = PI_2_F - p;
    if (x < 0.0f)  p = PI_F - p;
    p = copysignf(p, y);
    if (mx == 0.0f) p = 0.0f;         // atan2(0,0) = 0
    return p;
}

// ---------------------------------------------------------------------------
// Kernel 1: unnormalized Morlet taps (packed 4-row layout) + partial |w| sums.
// Grid (BB*FF, 8), 257 taps per sub-block.
// ---------------------------------------------------------------------------
__global__ void __launch_bounds__(256) k_wavelet(
    const float* __restrict__ fs,
    const float* __restrict__ freqs,
    const float* __restrict__ ncyc)
{
    int bf = blockIdx.x;            // b*32 + f
    int s  = blockIdx.y;            // sub-range 0..7
    int b = bf >> 5, f = bf & 31;
    float fc  = fmaxf(freqs[f], 0.1f);
    float nc  = fmaxf(ncyc[f], 1.0f);
    float fsb = fs[b];
    float omega = __fmul_rn(TWO_PI_F, fc);
    float sigma = __fdiv_rn(nc, omega);
    float d2    = __fmul_rn(2.0f, __fmul_rn(sigma, sigma));

    int g = f >> 2, r = f & 3;
    int Lw = group_L(g, fsb, freqs, ncyc) + 2;   // write window with guard

    int k_lo = s * 257;
    int k_hi = min(k_lo + 257, KK);

    __shared__ float sred[256];
    float part = 0.0f;

    float2* wbase = (float2*)&g_wav4[((size_t)(b * NGROUP + g) * KK) * 2];

    for (int k = k_lo + threadIdx.x; k < k_hi; k += 256) {
        float t   = (float)(k - HALF);
        float ts  = __fdiv_rn(t, fsb);
        float t2  = __fmul_rn(ts, ts);
        float q   = __fdiv_rn(-t2, d2);
        float env = expf(q);
        int m = k - HALF;
        if (m >= -Lw && m <= Lw) {
            float arg = __fmul_rn(omega, ts);
            float cs  = cosf(arg);
            float sn  = sinf(arg);
            float wr  = __fmul_rn(cs, env);
            float wi  = __fmul_rn(sn, env);
            wbase[k * 4 + r] = make_float2(wr, wi);
            part += sqrtf(__fadd_rn(__fmul_rn(wr, wr), __fmul_rn(wi, wi)));
        } else {
            part += env;   // |w| = env outside the window (dev ~1e-15 of norm)
        }
    }
    sred[threadIdx.x] = part;
    __syncthreads();
    for (int o = 128; o > 0; o >>= 1) {
        if (threadIdx.x < o) sred[threadIdx.x] = __fadd_rn(sred[threadIdx.x], sred[threadIdx.x + o]);
        __syncthreads();
    }
    if (threadIdx.x == 0) g_psum[bf * NW + s] = sred[0];
}

// ---------------------------------------------------------------------------
// Kernel 2: chunked sampled convolution (packed f32x2, single-level acc).
// x staged over the chunk's REACHABLE range only: t in [lo, 2047+hi], i.e.
// u = t - lo + BUFOFF <= 2048 + clen + BUFOFF <= 2257 (SKEW <= 2539 < 2600).
// ---------------------------------------------------------------------------
#define SKEW(a) ((a) + ((a) >> 3))

__global__ void __launch_bounds__(256, 4) k_conv(
    const float* __restrict__ x,
    const float* __restrict__ fs,
    const int*   __restrict__ seq_lens,
    const float* __restrict__ freqs,
    const float* __restrict__ ncyc)
{
    const int slot = blockIdx.x;    // 0..21
    const int c    = blockIdx.y;
    const int b    = blockIdx.z;
    const int g    = c_slot_g[slot];
    const int kk   = c_slot_k[slot];

    __shared__ float      xs[2600];           // skewed window buffer
    __shared__ ulonglong2 ws[2 * MAXCHUNK];   // staged weight chunk (32B/tap)

    const float fsb = fs[b];
    int L = group_L(g, fsb, freqs, ncyc);

    int taps = 2 * L + 1;
    int ncks = c_nchunk[g];
    int W  = (taps + ncks - 1) / ncks;
    int lo = -L + kk * W;
    int hi = min(lo + W, L + 1);
    int clen = hi - lo;                      // <= MAXCHUNK

    // ---- stage weight chunk ----
    {
        const float4* src = (const float4*)(g_wav4 + ((size_t)(b * NGROUP + g) * KK + (HALF + lo)) * 2);
        float4* dst = (float4*)ws;
        int n4 = clen * 2;
        for (int i = threadIdx.x; i < n4; i += 256) dst[i] = src[i];
    }

    // ---- x window: u(t) = t - lo + BUFOFF, needed t in [lo, 2047+hi] ----
    const float4* xrow4 = (const float4*)(x + ((size_t)b * CC + c) * TT);
    int t4s = max(0, lo) >> 2;
    int t_hi = min(TT - 1, TT - 1 + hi);     // clamp upper fill (hi<0 chunks!)
    int t4e = (t_hi >> 2) + 1;               // exclusive float4 bound
    for (int t4 = t4s + threadIdx.x; t4 < t4e; t4 += 256) {
        float4 v = xrow4[t4];
        int u0 = 4 * t4 - lo + BUFOFF;
        xs[SKEW(u0    )] = v.x;
        xs[SKEW(u0 + 1)] = v.y;
        xs[SKEW(u0 + 2)] = v.z;
        xs[SKEW(u0 + 3)] = v.w;
    }
    if (lo < 0) {                            // left zero pad: t in [lo, -1]
        for (int i = threadIdx.x; i < -lo; i += 256) {
            int u = i + BUFOFF;
            xs[SKEW(u)] = 0.0f;
        }
    }
    if (hi >= 0) {                           // right zero pad: t in [2048, 2048+hi]
        for (int d = threadIdx.x; d <= hi; d += 256) {
            int u = TT + d - lo + BUFOFF;
            xs[SKEW(u)] = 0.0f;
        }
    }
    __syncthreads();

    const int j   = threadIdx.x;
    const int seq = seq_lens[b];
    float gx = compute_gx(j, seq);
    int t0 = (int)floorf(gx);

    ull sum[8];
#pragma unroll
    for (int i = 0; i < 8; i++) sum[i] = 0ull;

    int a = t0 + BUFOFF;                     // u at m = lo
    const ulonglong2* wsp = ws;
    float xv0 = xs[SKEW(a)];

#pragma unroll 8
    for (int i = 0; i < clen; ++i) {
        int a1 = a + 1;
        float xv1 = xs[SKEW(a1)];
        ull p0 = pack2(xv0);
        ull p1 = pack2(xv1);
        ulonglong2 wa = wsp[0];
        ulonglong2 wb = wsp[1];
        sum[0] = ffma2(wa.x, p0, sum[0]);
        sum[1] = ffma2(wa.x, p1, sum[1]);
        sum[2] = ffma2(wa.y, p0, sum[2]);
        sum[3] = ffma2(wa.y, p1, sum[3]);
        sum[4] = ffma2(wb.x, p0, sum[4]);
        sum[5] = ffma2(wb.x, p1, sum[5]);
        sum[6] = ffma2(wb.y, p0, sum[6]);
        sum[7] = ffma2(wb.y, p1, sum[7]);
        xv0 = xv1; a = a1; wsp += 2;
    }

    // store partials: [b][c][slot][r][j] as float4 (v0.x, v0.y, v1.x, v1.y)
#pragma unroll
    for (int r = 0; r < RGROUP; r++) {
        float2 v0 = unpack2(sum[r * 2 + 0]);
        float2 v1 = unpack2(sum[r * 2 + 1]);
        size_t base = (((size_t)(b * CC + c) * NSLOT + slot) * RGROUP + r) * JJ + j;
        g_Vp[base] = make_float4(v0.x, v0.y, v1.x, v1.y);
    }
}

// ---------------------------------------------------------------------------
// Kernel 3: each thread reduces ONE row's chunk partials, exchanges via smem,
// then does bilinear + mag/phase. Grid (JJ/8, BB*CC), 256 thr = 32 rows x 8 tok.
// ---------------------------------------------------------------------------
__global__ void __launch_bounds__(256) k_out(
    const int* __restrict__ seq_lens,
    float* __restrict__ out)
{
    int bc = blockIdx.y;           // b*CC + c
    int b = bc >> 4, c = bc & 15;
    int tid = threadIdx.x;
    int f  = tid >> 3;             // row 0..31
    int jj = tid & 7;
    int j  = blockIdx.x * 8 + jj;

    __shared__ float s0x[289], s0y[289], s1x[289], s1y[289];

    int seq = seq_lens[b];
    float gx  = compute_gx(j, seq);
    float x0f = floorf(gx);
    int t0 = (int)x0f;
    int zero_x1 = (t0 + 1 >= TT);

    // ---- phase 1: reduce row f at token j ----
    {
        int g = f >> 2, r = f & 3;
        const float* ps = g_psum + (b * FF + f) * NW;
        float norm = ps[0];
#pragma unroll
        for (int k = 1; k < NW; ++k) norm = __fadd_rn(norm, ps[k]);
        norm = __fadd_rn(norm, 1e-8f);

        float2 s0 = make_float2(0.0f, 0.0f);
        float2 s1 = make_float2(0.0f, 0.0f);
        int ncks = c_nchunk[g], cb = c_cbase[g];
        for (int k = 0; k < ncks; ++k) {
            size_t base = (((size_t)(b * CC + c) * NSLOT + (cb + k)) * RGROUP + r) * JJ + j;
            float4 v = g_Vp[base];
            s0.x = __fadd_rn(s0.x, v.x);  s0.y = __fadd_rn(s0.y, v.y);
            s1.x = __fadd_rn(s1.x, v.z);  s1.y = __fadd_rn(s1.y, v.w);
        }
        if (zero_x1) s1 = make_float2(0.0f, 0.0f);
        int si = f * 9 + jj;
        s0x[si] = __fdiv_rn(s0.x, norm);
        s0y[si] = __fdiv_rn(s0.y, norm);
        s1x[si] = __fdiv_rn(s1.x, norm);
        s1y[si] = __fdiv_rn(s1.y, norm);
    }
    __syncthreads();

    // ---- phase 2: output element (f, j) ----
    // y coordinate — linspace(-1,1,32): fl(-1 + f*fl(2/31)), endpoint 1.0
    float stepy = __fdiv_rn(2.0f, 31.0f);
    float ylin  = (f == 31) ? 1.0f : __fadd_rn(-1.0f, __fmul_rn((float)f, stepy));
    float gyp   = __fmul_rn(__fmul_rn(__fadd_rn(ylin, 1.0f), 0.5f), 31.0f);
    float y0f   = floorf(gyp);
    float wy1   = __fadd_rn(gyp, -y0f);
    float wy0   = __fadd_rn(1.0f, -wy1);
    int y0 = (int)y0f;
    int y1 = y0 + 1;
    float val1 = (y1 <= FF - 1) ? 1.0f : 0.0f;
    int y1c = min(y1, FF - 1);
    int y0c = min(max(y0, 0), FF - 1);

    float wx1 = __fadd_rn(gx, -x0f);
    float wx0 = __fadd_rn(1.0f, -wx1);

    int si0 = y0c * 9 + jj;
    int si1 = y1c * 9 + jj;
    float2 v00 = make_float2(s0x[si0], s0y[si0]);
    float2 v01 = make_float2(s1x[si0], s1y[si0]);
    float2 v10 = make_float2(s0x[si1], s0y[si1]);
    float2 v11 = make_float2(s1x[si1], s1y[si1]);

    // reference order: ((g00*w00 + g01*w01) + g10*w10) + g11*w11
    float vr = __fadd_rn(__fadd_rn(__fadd_rn(
                 __fmul_rn(v00.x, __fmul_rn(wy0, wx0)),
                 __fmul_rn(v01.x, __fmul_rn(wy0, wx1))),
                 __fmul_rn(__fmul_rn(v10.x, val1), __fmul_rn(wy1, wx0))),
                 __fmul_rn(__fmul_rn(v11.x, val1), __fmul_rn(wy1, wx1)));
    float vi = __fadd_rn(__fadd_rn(__fadd_rn(
                 __fmul_rn(v00.y, __fmul_rn(wy0, wx0)),
                 __fmul_rn(v01.y, __fmul_rn(wy0, wx1))),
                 __fmul_rn(__fmul_rn(v10.y, val1), __fmul_rn(wy1, wx0))),
                 __fmul_rn(__fmul_rn(v11.y, val1), __fmul_rn(wy1, wx1)));

    float mag = sqrtf(__fadd_rn(__fadd_rn(__fmul_rn(vr, vr), __fmul_rn(vi, vi)), 1e-8f));
    float ph  = __fdiv_rn(fast_atan2(vi, vr), PI_F);

    size_t ob = (((size_t)(b * CC + c) * 2 + 0) * FF + f) * JJ + j;
    out[ob] = mag;
    out[ob + (size_t)FF * JJ] = ph;
}

// ---------------------------------------------------------------------------
extern "C" void kernel_launch(void* const* d_in, const int* in_sizes, int n_in,
                              void* d_out, int out_size)
{
    const float* x        = (const float*)d_in[0];  // (4,16,2048)
    const float* fs       = (const float*)d_in[1];  // (4,)
    const int*   seq_lens = (const int*)  d_in[2];  // (4,)
    const float* freqs    = (const float*)d_in[3];  // (32,)
    const float* ncyc     = (const float*)d_in[4];  // (32,)
    float* out = (float*)d_out;                     // (4,16,2,32,256)

    k_wavelet<<<dim3(BB * FF, NW), 256>>>(fs, freqs, ncyc);
    k_conv<<<dim3(NSLOT, CC, BB), 256>>>(x, fs, seq_lens, freqs, ncyc);
    k_out<<<dim3(JJ / 8, BB * CC), 256>>>(seq_lens, out);
}